// round 3
// baseline (speedup 1.0000x reference)
#include <cuda_runtime.h>

// ---------------------------------------------------------------------------
// Problem constants
// ---------------------------------------------------------------------------
constexpr int kB = 8;
constexpr int kT = 1024;
constexpr int kD = 1024;          // n_embd
constexpr int kH = 16;            // heads
constexpr int kE = 64;            // head size
constexpr int kF = 4096;          // ffn hidden
constexpr int kM = kB * kT;       // 8192 rows
constexpr int kQKVN = 3 * kD;     // 3072

// ---------------------------------------------------------------------------
// Scratch (device globals: allocation-free per harness rules)
// ---------------------------------------------------------------------------
__device__ float g_ln1[(size_t)kM * kD];
__device__ float g_wt [(size_t)kD * kQKVN];
__device__ float g_qkv[(size_t)kM * kQKVN];
__device__ float g_att[(size_t)kM * kD];
__device__ float g_x2 [(size_t)kM * kD];
__device__ float g_ln2[(size_t)kM * kD];
__device__ float g_hid[(size_t)kM * kF];

// ---------------------------------------------------------------------------
// LayerNorm: one block per row of 1024, 256 threads, float4 per thread
// ---------------------------------------------------------------------------
__global__ __launch_bounds__(256) void ln_kernel(
    const float* __restrict__ x, const float* __restrict__ g,
    const float* __restrict__ b, float* __restrict__ out)
{
    int row = blockIdx.x;
    int tid = threadIdx.x;
    const float* xr = x + (size_t)row * kD;
    float*       orow = out + (size_t)row * kD;

    float4 v = *reinterpret_cast<const float4*>(&xr[tid * 4]);
    float s  = v.x + v.y + v.z + v.w;
    float s2 = v.x * v.x + v.y * v.y + v.z * v.z + v.w * v.w;
    #pragma unroll
    for (int o = 16; o > 0; o >>= 1) {
        s  += __shfl_xor_sync(0xffffffffu, s,  o);
        s2 += __shfl_xor_sync(0xffffffffu, s2, o);
    }
    __shared__ float red[16];
    __shared__ float sh_mean, sh_rstd;
    int w = tid >> 5, l = tid & 31;
    if (l == 0) { red[w] = s; red[8 + w] = s2; }
    __syncthreads();
    if (tid == 0) {
        float S = 0.f, S2 = 0.f;
        #pragma unroll
        for (int i = 0; i < 8; i++) { S += red[i]; S2 += red[8 + i]; }
        float mean = S * (1.0f / kD);
        float var  = S2 * (1.0f / kD) - mean * mean;
        sh_mean = mean;
        sh_rstd = rsqrtf(var + 1e-5f);
    }
    __syncthreads();
    float mean = sh_mean, rstd = sh_rstd;
    float4 gv = *reinterpret_cast<const float4*>(&g[tid * 4]);
    float4 bv = *reinterpret_cast<const float4*>(&b[tid * 4]);
    float4 o4;
    o4.x = (v.x - mean) * rstd * gv.x + bv.x;
    o4.y = (v.y - mean) * rstd * gv.y + bv.y;
    o4.z = (v.z - mean) * rstd * gv.z + bv.z;
    o4.w = (v.w - mean) * rstd * gv.w + bv.w;
    *reinterpret_cast<float4*>(&orow[tid * 4]) = o4;
}

// ---------------------------------------------------------------------------
// Transpose wq/wk/wv [H,D,E] -> combined [D, 3072] (Q cols 0..1023, K, V)
// ---------------------------------------------------------------------------
__global__ __launch_bounds__(256) void wqkv_transpose_kernel(
    const float* __restrict__ wq, const float* __restrict__ wk,
    const float* __restrict__ wv, float* __restrict__ wt)
{
    int idx = blockIdx.x * 256 + threadIdx.x;          // < 3 * H*D*E
    int sec = idx / (kH * kD * kE);
    int r   = idx - sec * (kH * kD * kE);
    int h   = r / (kD * kE);
    int rem = r - h * (kD * kE);
    int d   = rem / kE;
    int e   = rem - d * kE;
    const float* w = (sec == 0) ? wq : (sec == 1) ? wk : wv;
    wt[(size_t)d * kQKVN + sec * kD + h * kE + e] = w[r];
}

// ---------------------------------------------------------------------------
// Tiled SGEMM: C[M,N] = A[M,K] @ B[K,N] (+bias col) (+res elementwise) (relu)
// 128x128 block tile, BK=8, 256 threads, 8x8 micro-tile.
// M,N multiples of 128; K multiple of 8 (all true here).
// ---------------------------------------------------------------------------
template <int RELU>
__global__ __launch_bounds__(256) void sgemm_kernel(
    const float* __restrict__ A, const float* __restrict__ Bm,
    const float* __restrict__ bias, const float* __restrict__ res,
    float* __restrict__ C, int M, int N, int K)
{
    __shared__ float As[8][128];
    __shared__ float Bs[8][128];

    int tid = threadIdx.x;
    int tx = tid & 15;            // 16 cols of threads
    int ty = tid >> 4;            // 16 rows of threads
    const float* Ab = A + (size_t)blockIdx.y * 128 * K;
    const float* Bb = Bm + (size_t)blockIdx.x * 128;

    float acc[8][8];
    #pragma unroll
    for (int i = 0; i < 8; i++)
        #pragma unroll
        for (int j = 0; j < 8; j++) acc[i][j] = 0.f;

    for (int k0 = 0; k0 < K; k0 += 8) {
        #pragma unroll
        for (int i = tid; i < 1024; i += 256) {
            int r = i >> 3, c = i & 7;
            As[c][r] = Ab[(size_t)r * K + k0 + c];
        }
        #pragma unroll
        for (int i = tid; i < 1024; i += 256) {
            int r = i >> 7, c = i & 127;
            Bs[r][c] = Bb[(size_t)(k0 + r) * N + c];
        }
        __syncthreads();

        #pragma unroll
        for (int kk = 0; kk < 8; kk++) {
            float4 a0 = *reinterpret_cast<const float4*>(&As[kk][ty * 8]);
            float4 a1 = *reinterpret_cast<const float4*>(&As[kk][ty * 8 + 4]);
            float4 b0 = *reinterpret_cast<const float4*>(&Bs[kk][tx * 8]);
            float4 b1 = *reinterpret_cast<const float4*>(&Bs[kk][tx * 8 + 4]);
            float av[8] = {a0.x, a0.y, a0.z, a0.w, a1.x, a1.y, a1.z, a1.w};
            float bv[8] = {b0.x, b0.y, b0.z, b0.w, b1.x, b1.y, b1.z, b1.w};
            #pragma unroll
            for (int i = 0; i < 8; i++)
                #pragma unroll
                for (int j = 0; j < 8; j++)
                    acc[i][j] += av[i] * bv[j];
        }
        __syncthreads();
    }

    int row0 = blockIdx.y * 128 + ty * 8;
    int col0 = blockIdx.x * 128 + tx * 8;
    #pragma unroll
    for (int i = 0; i < 8; i++) {
        size_t r = (size_t)(row0 + i);
        #pragma unroll
        for (int jj = 0; jj < 2; jj++) {
            int c = col0 + jj * 4;
            float4 o;
            o.x = acc[i][jj * 4 + 0];
            o.y = acc[i][jj * 4 + 1];
            o.z = acc[i][jj * 4 + 2];
            o.w = acc[i][jj * 4 + 3];
            if (bias) {
                float4 bb4 = *reinterpret_cast<const float4*>(&bias[c]);
                o.x += bb4.x; o.y += bb4.y; o.z += bb4.z; o.w += bb4.w;
            }
            if (res) {
                float4 r4 = *reinterpret_cast<const float4*>(&res[r * N + c]);
                o.x += r4.x; o.y += r4.y; o.z += r4.z; o.w += r4.w;
            }
            if (RELU) {
                o.x = fmaxf(o.x, 0.f); o.y = fmaxf(o.y, 0.f);
                o.z = fmaxf(o.z, 0.f); o.w = fmaxf(o.w, 0.f);
            }
            *reinterpret_cast<float4*>(&C[r * N + c]) = o;
        }
    }
}

// ---------------------------------------------------------------------------
// Causal flash attention. QKV combined [M, 3072] rows (Q|K|V each 1024 cols,
// head h at cols h*64..h*64+63). One block = 64 query rows of one (b,h).
// 256 threads as 16x16, 4x4 micro-tile for both S=QK^T and O+=PV.
// smem tiles pitch 68 for conflict-free float4 access.
// ---------------------------------------------------------------------------
constexpr int AP = 68;
constexpr int ATTN_SMEM = (4 * 64 * AP + 3 * 64) * (int)sizeof(float);  // 70400 B

__global__ __launch_bounds__(256) void attn_kernel(
    const float* __restrict__ QKV, float* __restrict__ O)
{
    extern __shared__ float sm[];
    float* Qs   = sm;                       // [64][AP]  (row-major: [q][e])
    float* Ks   = sm + 64 * AP;             // [64][AP]  transposed: [e][key]
    float* Vs   = sm + 2 * 64 * AP;         // [64][AP]  [key][e]
    float* Ps   = sm + 3 * 64 * AP;         // [64][AP]  scores / probs [q][key]
    float* mrow = sm + 4 * 64 * AP;         // [64]
    float* lrow = mrow + 64;                // [64]
    float* cf   = lrow + 64;                // [64]

    int qb = blockIdx.x, h = blockIdx.y, b = blockIdx.z;
    int tid = threadIdx.x;
    int tx = tid & 15, ty = tid >> 4;

    const size_t rs = (size_t)kQKVN;
    const float* Qbase = QKV + (size_t)(b * kT) * rs + h * kE;
    const float* Kbase = Qbase + kD;
    const float* Vbase = Qbase + 2 * kD;

    // Load Q tile
    #pragma unroll
    for (int i = tid; i < 64 * 64; i += 256) {
        int r = i >> 6, e = i & 63;
        Qs[r * AP + e] = Qbase[(size_t)(qb * 64 + r) * rs + e];
    }
    if (tid < 64) { mrow[tid] = -1e30f; lrow[tid] = 0.f; }

    float acc[4][4];
    #pragma unroll
    for (int i = 0; i < 4; i++)
        #pragma unroll
        for (int j = 0; j < 4; j++) acc[i][j] = 0.f;
    __syncthreads();

    const float scale = 0.125f;  // 1/sqrt(64)

    for (int j0 = 0; j0 <= qb * 64; j0 += 64) {
        // Load K (transposed into [e][key]) and V ([key][e])
        #pragma unroll
        for (int i = tid; i < 64 * 64; i += 256) {
            int r = i >> 6, e = i & 63;
            Ks[e * AP + r] = Kbase[(size_t)(j0 + r) * rs + e];
            Vs[r * AP + e] = Vbase[(size_t)(j0 + r) * rs + e];
        }
        __syncthreads();

        // S = Q K^T
        float s[4][4];
        #pragma unroll
        for (int i = 0; i < 4; i++)
            #pragma unroll
            for (int j = 0; j < 4; j++) s[i][j] = 0.f;

        #pragma unroll
        for (int kk = 0; kk < 64; kk += 4) {
            float4 b0 = *reinterpret_cast<const float4*>(&Ks[(kk + 0) * AP + tx * 4]);
            float4 b1 = *reinterpret_cast<const float4*>(&Ks[(kk + 1) * AP + tx * 4]);
            float4 b2 = *reinterpret_cast<const float4*>(&Ks[(kk + 2) * AP + tx * 4]);
            float4 b3 = *reinterpret_cast<const float4*>(&Ks[(kk + 3) * AP + tx * 4]);
            #pragma unroll
            for (int i = 0; i < 4; i++) {
                float4 a = *reinterpret_cast<const float4*>(&Qs[(ty * 4 + i) * AP + kk]);
                s[i][0] += a.x * b0.x + a.y * b1.x + a.z * b2.x + a.w * b3.x;
                s[i][1] += a.x * b0.y + a.y * b1.y + a.z * b2.y + a.w * b3.y;
                s[i][2] += a.x * b0.z + a.y * b1.z + a.z * b2.z + a.w * b3.z;
                s[i][3] += a.x * b0.w + a.y * b1.w + a.z * b2.w + a.w * b3.w;
            }
        }

        // scale + causal mask + store to Ps
        #pragma unroll
        for (int i = 0; i < 4; i++) {
            int gr = qb * 64 + ty * 4 + i;
            #pragma unroll
            for (int j = 0; j < 4; j++) {
                int gc = j0 + tx * 4 + j;
                float v = s[i][j] * scale;
                if (gc > gr) v = -1e30f;
                Ps[(ty * 4 + i) * AP + tx * 4 + j] = v;
            }
        }
        __syncthreads();

        // Online softmax (one thread per row)
        if (tid < 64) {
            int r = tid;
            float mold = mrow[r];
            float mx = mold;
            #pragma unroll 8
            for (int k = 0; k < 64; k++) mx = fmaxf(mx, Ps[r * AP + k]);
            float c = __expf(mold - mx);
            float sum = 0.f;
            #pragma unroll 8
            for (int k = 0; k < 64; k++) {
                float p = __expf(Ps[r * AP + k] - mx);
                Ps[r * AP + k] = p;
                sum += p;
            }
            lrow[r] = lrow[r] * c + sum;
            mrow[r] = mx;
            cf[r] = c;
        }
        __syncthreads();

        // O = O*c + P @ V
        #pragma unroll
        for (int i = 0; i < 4; i++) {
            float ci = cf[ty * 4 + i];
            #pragma unroll
            for (int j = 0; j < 4; j++) acc[i][j] *= ci;
        }
        #pragma unroll
        for (int kk = 0; kk < 64; kk += 4) {
            float4 v0 = *reinterpret_cast<const float4*>(&Vs[(kk + 0) * AP + tx * 4]);
            float4 v1 = *reinterpret_cast<const float4*>(&Vs[(kk + 1) * AP + tx * 4]);
            float4 v2 = *reinterpret_cast<const float4*>(&Vs[(kk + 2) * AP + tx * 4]);
            float4 v3 = *reinterpret_cast<const float4*>(&Vs[(kk + 3) * AP + tx * 4]);
            #pragma unroll
            for (int i = 0; i < 4; i++) {
                float4 p = *reinterpret_cast<const float4*>(&Ps[(ty * 4 + i) * AP + kk]);
                acc[i][0] += p.x * v0.x + p.y * v1.x + p.z * v2.x + p.w * v3.x;
                acc[i][1] += p.x * v0.y + p.y * v1.y + p.z * v2.y + p.w * v3.y;
                acc[i][2] += p.x * v0.z + p.y * v1.z + p.z * v2.z + p.w * v3.z;
                acc[i][3] += p.x * v0.w + p.y * v1.w + p.z * v2.w + p.w * v3.w;
            }
        }
        __syncthreads();
    }

    // Normalize and write out (concat-head layout: col = h*64 + e)
    #pragma unroll
    for (int i = 0; i < 4; i++) {
        int t = qb * 64 + ty * 4 + i;
        float inv = 1.0f / lrow[ty * 4 + i];
        float4 o;
        o.x = acc[i][0] * inv;
        o.y = acc[i][1] * inv;
        o.z = acc[i][2] * inv;
        o.w = acc[i][3] * inv;
        *reinterpret_cast<float4*>(
            &O[(size_t)(b * kT + t) * kD + h * kE + tx * 4]) = o;
    }
}

// ---------------------------------------------------------------------------
// Launch
// ---------------------------------------------------------------------------
extern "C" void kernel_launch(void* const* d_in, const int* in_sizes, int n_in,
                              void* d_out, int out_size)
{
    const float* x      = (const float*)d_in[0];
    const float* wq     = (const float*)d_in[1];
    const float* wk     = (const float*)d_in[2];
    const float* wv     = (const float*)d_in[3];
    const float* w_proj = (const float*)d_in[4];
    const float* b_proj = (const float*)d_in[5];
    const float* w1     = (const float*)d_in[6];
    const float* b1     = (const float*)d_in[7];
    const float* w2     = (const float*)d_in[8];
    const float* b2     = (const float*)d_in[9];
    const float* g1     = (const float*)d_in[10];
    const float* be1    = (const float*)d_in[11];
    const float* g2     = (const float*)d_in[12];
    const float* be2    = (const float*)d_in[13];
    float* out = (float*)d_out;

    float *ln1, *wt, *qkv, *att, *x2, *ln2, *hid;
    cudaGetSymbolAddress((void**)&ln1, g_ln1);
    cudaGetSymbolAddress((void**)&wt,  g_wt);
    cudaGetSymbolAddress((void**)&qkv, g_qkv);
    cudaGetSymbolAddress((void**)&att, g_att);
    cudaGetSymbolAddress((void**)&x2,  g_x2);
    cudaGetSymbolAddress((void**)&ln2, g_ln2);
    cudaGetSymbolAddress((void**)&hid, g_hid);

    cudaFuncSetAttribute(attn_kernel,
                         cudaFuncAttributeMaxDynamicSharedMemorySize, ATTN_SMEM);

    // 1) LN1
    ln_kernel<<<kM, 256>>>(x, g1, be1, ln1);

    // 2) QKV weight transpose + fused QKV GEMM  [8192,1024] @ [1024,3072]
    wqkv_transpose_kernel<<<(3 * kH * kD * kE) / 256, 256>>>(wq, wk, wv, wt);
    sgemm_kernel<0><<<dim3(kQKVN / 128, kM / 128), 256>>>(
        ln1, wt, nullptr, nullptr, qkv, kM, kQKVN, kD);

    // 3) Causal flash attention
    attn_kernel<<<dim3(kT / 64, kH, kB), 256, ATTN_SMEM>>>(qkv, att);

    // 4) Output projection + bias + residual(ln1)
    sgemm_kernel<0><<<dim3(kD / 128, kM / 128), 256>>>(
        att, w_proj, b_proj, ln1, x2, kM, kD, kD);

    // 5) LN2
    ln_kernel<<<kM, 256>>>(x2, g2, be2, ln2);

    // 6) FFN1 with ReLU
    sgemm_kernel<1><<<dim3(kF / 128, kM / 128), 256>>>(
        ln2, w1, b1, nullptr, hid, kM, kF, kD);

    // 7) FFN2 + bias + residual(ln2) -> output
    sgemm_kernel<0><<<dim3(kD / 128, kM / 128), 256>>>(
        hid, w2, b2, ln2, out, kM, kD, kF);
}

// round 7
// speedup vs baseline: 5.4731x; 5.4731x over previous
#include <cuda_runtime.h>
#include <cuda_fp16.h>
#include <cstdint>

// ---------------------------------------------------------------------------
// Problem constants
// ---------------------------------------------------------------------------
constexpr int kB = 8;
constexpr int kT = 1024;
constexpr int kD = 1024;          // n_embd
constexpr int kH = 16;            // heads
constexpr int kE = 64;            // head size
constexpr int kF = 4096;          // ffn hidden
constexpr int kM = kB * kT;       // 8192 rows
constexpr int kQKVN = 3 * kD;     // 3072

// ---------------------------------------------------------------------------
// Scratch (device globals: allocation-free per harness rules)
// ---------------------------------------------------------------------------
__device__ __align__(16) float  g_ln1f[(size_t)kM * kD];
__device__ __align__(16) __half g_ln1h[(size_t)kM * kD];
__device__ __align__(16) float  g_qkv [(size_t)kM * kQKVN];
__device__ __align__(16) __half g_atth[(size_t)kM * kD];
__device__ __align__(16) float  g_x2  [(size_t)kM * kD];
__device__ __align__(16) float  g_ln2f[(size_t)kM * kD];
__device__ __align__(16) __half g_ln2h[(size_t)kM * kD];
__device__ __align__(16) __half g_hidh[(size_t)kM * kF];
__device__ __align__(16) __half g_wqkv[(size_t)kQKVN * kD];   // [N=3072][K=1024]
__device__ __align__(16) __half g_wp  [(size_t)kD * kD];      // [N=1024][K=1024]
__device__ __align__(16) __half g_w1t [(size_t)kF * kD];      // [N=4096][K=1024]
__device__ __align__(16) __half g_w2t [(size_t)kD * kF];      // [N=1024][K=4096]

// ---------------------------------------------------------------------------
// Low-level helpers
// ---------------------------------------------------------------------------
__device__ __forceinline__ uint32_t smem_u32(const void* p) {
    uint32_t r;
    asm("{ .reg .u64 t; cvta.to.shared.u64 t, %1; cvt.u32.u64 %0, t; }"
        : "=r"(r) : "l"(p));
    return r;
}

__device__ __forceinline__ void cp_async16(uint32_t dst, const void* src) {
    asm volatile("cp.async.cg.shared.global [%0], [%1], 16;"
                 :: "r"(dst), "l"(src));
}

__device__ __forceinline__ void ldmatrix_x4(uint32_t* r, uint32_t addr) {
    asm volatile("ldmatrix.sync.aligned.m8n8.x4.shared.b16 {%0,%1,%2,%3}, [%4];"
                 : "=r"(r[0]), "=r"(r[1]), "=r"(r[2]), "=r"(r[3]) : "r"(addr));
}

__device__ __forceinline__ void mma16816(float* d,
                                         const uint32_t* a, const uint32_t* b) {
    asm volatile(
        "mma.sync.aligned.m16n8k16.row.col.f32.f16.f16.f32 "
        "{%0,%1,%2,%3}, {%4,%5,%6,%7}, {%8,%9}, {%0,%1,%2,%3};"
        : "+f"(d[0]), "+f"(d[1]), "+f"(d[2]), "+f"(d[3])
        : "r"(a[0]), "r"(a[1]), "r"(a[2]), "r"(a[3]), "r"(b[0]), "r"(b[1]));
}

// ---------------------------------------------------------------------------
// HMMA GEMM: C[M,N] = A_h[M,K] @ B_h[N,K]^T  (+bias) (+res) (relu)
// 128x128 block tile, BK=64, 3-stage cp.async pipeline, 256 threads (8 warps,
// 64x32 warp tiles). Smem tiles: 128 rows x 128B, XOR-swizzled for
// conflict-free ldmatrix.
// ---------------------------------------------------------------------------
constexpr int GEMM_SMEM = 3 * 32768;   // 96 KB

template <int RELU, int W32, int W16>
__global__ __launch_bounds__(256)
void gemm_mma(const __half* __restrict__ A, const __half* __restrict__ B,
              const float* __restrict__ bias, const float* __restrict__ res,
              float* __restrict__ C32, __half* __restrict__ C16,
              int M, int N, int K)
{
    extern __shared__ char smem[];
    uint32_t sb = smem_u32(smem);

    const int tid  = threadIdx.x;
    const int wid  = tid >> 5;
    const int lane = tid & 31;
    const int wm = (wid & 1) * 64;        // warp row offset in tile
    const int wn = (wid >> 1) * 32;       // warp col offset in tile
    const int row0 = blockIdx.y * 128;
    const int col0 = blockIdx.x * 128;
    const __half* Ab = A + (size_t)row0 * K;
    const __half* Bb = B + (size_t)col0 * K;
    const int nch = K >> 6;               // chunks of K=64

    auto load_chunk = [&](int c, int s) {
        uint32_t base = sb + (uint32_t)s * 32768u;
        const __half* Ap = Ab + c * 64;
        const __half* Bp = Bb + c * 64;
        #pragma unroll
        for (int j = 0; j < 4; j++) {
            int idx = tid + j * 256;              // 0..1023
            int r  = idx >> 3;
            int cc = idx & 7;
            uint32_t off = (uint32_t)(r * 128 + ((cc ^ (r & 7)) << 4));
            cp_async16(base + off,         Ap + (size_t)r * K + cc * 8);
            cp_async16(base + 16384 + off, Bp + (size_t)r * K + cc * 8);
        }
        asm volatile("cp.async.commit_group;" ::: "memory");
    };

    float acc[4][4][4];
    #pragma unroll
    for (int i = 0; i < 4; i++)
        #pragma unroll
        for (int j = 0; j < 4; j++)
            #pragma unroll
            for (int q = 0; q < 4; q++) acc[i][j][q] = 0.f;

    load_chunk(0, 0);
    load_chunk(1, 1);

    for (int i = 0; i < nch; i++) {
        if (i < nch - 1) asm volatile("cp.async.wait_group 1;" ::: "memory");
        else             asm volatile("cp.async.wait_group 0;" ::: "memory");
        __syncthreads();

        if (i + 2 < nch) load_chunk(i + 2, (i + 2) % 3);

        uint32_t abase = sb + (uint32_t)(i % 3) * 32768u;
        uint32_t bbase = abase + 16384;

        #pragma unroll
        for (int kk = 0; kk < 4; kk++) {          // 4 k-steps of 16
            uint32_t af[4][4];
            #pragma unroll
            for (int mt = 0; mt < 4; mt++) {
                int m  = wm + mt * 16 + (lane & 7) + ((lane >> 3) & 1) * 8;
                int kc = kk * 2 + (lane >> 4);
                ldmatrix_x4(af[mt],
                            abase + (uint32_t)(m * 128 + ((kc ^ (m & 7)) << 4)));
            }
            uint32_t bf[2][4];
            #pragma unroll
            for (int nb = 0; nb < 2; nb++) {
                int n  = wn + nb * 16 + (lane & 7) + (lane >> 4) * 8;
                int kc = kk * 2 + ((lane >> 3) & 1);
                ldmatrix_x4(bf[nb],
                            bbase + (uint32_t)(n * 128 + ((kc ^ (n & 7)) << 4)));
            }
            #pragma unroll
            for (int mt = 0; mt < 4; mt++)
                #pragma unroll
                for (int nt = 0; nt < 4; nt++)
                    mma16816(acc[mt][nt], af[mt], bf[nt >> 1] + (nt & 1) * 2);
        }
    }

    // Epilogue (accum layout: c0,c1 at row lane>>2, cols (lane&3)*2+{0,1};
    // c2,c3 at row+8)
    #pragma unroll
    for (int mt = 0; mt < 4; mt++) {
        #pragma unroll
        for (int h = 0; h < 2; h++) {
            int r = row0 + wm + mt * 16 + (lane >> 2) + h * 8;
            size_t rowN = (size_t)r * N;
            #pragma unroll
            for (int nt = 0; nt < 4; nt++) {
                int c = col0 + wn + nt * 8 + (lane & 3) * 2;
                float v0 = acc[mt][nt][h * 2 + 0];
                float v1 = acc[mt][nt][h * 2 + 1];
                if (bias) { v0 += bias[c]; v1 += bias[c + 1]; }
                if (res) {
                    float2 r2 = *reinterpret_cast<const float2*>(res + rowN + c);
                    v0 += r2.x; v1 += r2.y;
                }
                if (RELU) { v0 = fmaxf(v0, 0.f); v1 = fmaxf(v1, 0.f); }
                if (W32) {
                    float2 o = make_float2(v0, v1);
                    *reinterpret_cast<float2*>(C32 + rowN + c) = o;
                }
                if (W16) {
                    __half2 hh = __floats2half2_rn(v0, v1);
                    *reinterpret_cast<__half2*>(C16 + rowN + c) = hh;
                }
            }
        }
    }
}

// ---------------------------------------------------------------------------
// LayerNorm: one block per row of 1024; writes fp32 + fp16
// ---------------------------------------------------------------------------
__global__ __launch_bounds__(256) void ln_kernel(
    const float* __restrict__ x, const float* __restrict__ g,
    const float* __restrict__ b, float* __restrict__ outf,
    __half* __restrict__ outh)
{
    int row = blockIdx.x;
    int tid = threadIdx.x;
    const float* xr = x + (size_t)row * kD;

    float4 v = *reinterpret_cast<const float4*>(&xr[tid * 4]);
    float s  = v.x + v.y + v.z + v.w;
    float s2 = v.x * v.x + v.y * v.y + v.z * v.z + v.w * v.w;
    #pragma unroll
    for (int o = 16; o > 0; o >>= 1) {
        s  += __shfl_xor_sync(0xffffffffu, s,  o);
        s2 += __shfl_xor_sync(0xffffffffu, s2, o);
    }
    __shared__ float red[16];
    __shared__ float sh_mean, sh_rstd;
    int w = tid >> 5, l = tid & 31;
    if (l == 0) { red[w] = s; red[8 + w] = s2; }
    __syncthreads();
    if (tid == 0) {
        float S = 0.f, S2 = 0.f;
        #pragma unroll
        for (int i = 0; i < 8; i++) { S += red[i]; S2 += red[8 + i]; }
        float mean = S * (1.0f / kD);
        float var  = S2 * (1.0f / kD) - mean * mean;
        sh_mean = mean;
        sh_rstd = rsqrtf(var + 1e-5f);
    }
    __syncthreads();
    float mean = sh_mean, rstd = sh_rstd;
    float4 gv = *reinterpret_cast<const float4*>(&g[tid * 4]);
    float4 bv = *reinterpret_cast<const float4*>(&b[tid * 4]);
    float4 o4;
    o4.x = (v.x - mean) * rstd * gv.x + bv.x;
    o4.y = (v.y - mean) * rstd * gv.y + bv.y;
    o4.z = (v.z - mean) * rstd * gv.z + bv.z;
    o4.w = (v.w - mean) * rstd * gv.w + bv.w;
    *reinterpret_cast<float4*>(&outf[(size_t)row * kD + tid * 4]) = o4;
    __half2 h0 = __floats2half2_rn(o4.x, o4.y);
    __half2 h1 = __floats2half2_rn(o4.z, o4.w);
    uint2 u = make_uint2(*reinterpret_cast<uint32_t*>(&h0),
                         *reinterpret_cast<uint32_t*>(&h1));
    *reinterpret_cast<uint2*>(&outh[(size_t)row * kD + tid * 4]) = u;
}

// ---------------------------------------------------------------------------
// Weight transpose+convert: wq/wk/wv [H,D,E] f32 -> [N=3072][K=1024] f16
// ---------------------------------------------------------------------------
__global__ __launch_bounds__(256) void wqkv_t_kernel(
    const float* __restrict__ wq, const float* __restrict__ wk,
    const float* __restrict__ wv, __half* __restrict__ out)
{
    __shared__ float tile[32][33];
    int z = blockIdx.z;
    int sec = z >> 4, h = z & 15;
    const float* in = ((sec == 0) ? wq : (sec == 1) ? wk : wv) +
                      (size_t)h * kD * kE;
    int d0 = blockIdx.x * 32, e0 = blockIdx.y * 32;
    int x = threadIdx.x & 31, y0 = threadIdx.x >> 5;   // y0 in 0..7
    #pragma unroll
    for (int j = 0; j < 32; j += 8)
        tile[y0 + j][x] = in[(size_t)(d0 + y0 + j) * kE + e0 + x];
    __syncthreads();
    #pragma unroll
    for (int j = 0; j < 32; j += 8)
        out[(size_t)(sec * kD + h * kE + e0 + y0 + j) * kD + d0 + x] =
            __float2half(tile[x][y0 + j]);
}

// Generic transpose+convert: in [R,C] f32 -> out [C,R] f16
__global__ __launch_bounds__(256) void tr_kernel(
    const float* __restrict__ in, __half* __restrict__ out, int R, int C)
{
    __shared__ float tile[32][33];
    int r0 = blockIdx.y * 32, c0 = blockIdx.x * 32;
    int x = threadIdx.x & 31, y0 = threadIdx.x >> 5;
    #pragma unroll
    for (int j = 0; j < 32; j += 8)
        tile[y0 + j][x] = in[(size_t)(r0 + y0 + j) * C + c0 + x];
    __syncthreads();
    #pragma unroll
    for (int j = 0; j < 32; j += 8)
        out[(size_t)(c0 + y0 + j) * R + r0 + x] = __float2half(tile[x][y0 + j]);
}

// ---------------------------------------------------------------------------
// Causal flash attention (fp32 math; output converted to f16)
// ---------------------------------------------------------------------------
constexpr int AP = 68;
constexpr int ATTN_SMEM = (4 * 64 * AP + 3 * 64) * (int)sizeof(float);

__global__ __launch_bounds__(256) void attn_kernel(
    const float* __restrict__ QKV, __half* __restrict__ O)
{
    extern __shared__ float sm[];
    float* Qs   = sm;
    float* Ks   = sm + 64 * AP;
    float* Vs   = sm + 2 * 64 * AP;
    float* Ps   = sm + 3 * 64 * AP;
    float* mrow = sm + 4 * 64 * AP;
    float* lrow = mrow + 64;
    float* cf   = lrow + 64;

    int qb = blockIdx.x, h = blockIdx.y, b = blockIdx.z;
    int tid = threadIdx.x;
    int tx = tid & 15, ty = tid >> 4;

    const size_t rs = (size_t)kQKVN;
    const float* Qbase = QKV + (size_t)(b * kT) * rs + h * kE;
    const float* Kbase = Qbase + kD;
    const float* Vbase = Qbase + 2 * kD;

    #pragma unroll
    for (int i = tid; i < 64 * 64; i += 256) {
        int r = i >> 6, e = i & 63;
        Qs[r * AP + e] = Qbase[(size_t)(qb * 64 + r) * rs + e];
    }
    if (tid < 64) { mrow[tid] = -1e30f; lrow[tid] = 0.f; }

    float acc[4][4];
    #pragma unroll
    for (int i = 0; i < 4; i++)
        #pragma unroll
        for (int j = 0; j < 4; j++) acc[i][j] = 0.f;
    __syncthreads();

    const float scale = 0.125f;

    for (int j0 = 0; j0 <= qb * 64; j0 += 64) {
        #pragma unroll
        for (int i = tid; i < 64 * 64; i += 256) {
            int r = i >> 6, e = i & 63;
            Ks[e * AP + r] = Kbase[(size_t)(j0 + r) * rs + e];
            Vs[r * AP + e] = Vbase[(size_t)(j0 + r) * rs + e];
        }
        __syncthreads();

        float s[4][4];
        #pragma unroll
        for (int i = 0; i < 4; i++)
            #pragma unroll
            for (int j = 0; j < 4; j++) s[i][j] = 0.f;

        #pragma unroll
        for (int kk = 0; kk < 64; kk += 4) {
            float4 b0 = *reinterpret_cast<const float4*>(&Ks[(kk + 0) * AP + tx * 4]);
            float4 b1 = *reinterpret_cast<const float4*>(&Ks[(kk + 1) * AP + tx * 4]);
            float4 b2 = *reinterpret_cast<const float4*>(&Ks[(kk + 2) * AP + tx * 4]);
            float4 b3 = *reinterpret_cast<const float4*>(&Ks[(kk + 3) * AP + tx * 4]);
            #pragma unroll
            for (int i = 0; i < 4; i++) {
                float4 a = *reinterpret_cast<const float4*>(&Qs[(ty * 4 + i) * AP + kk]);
                s[i][0] += a.x * b0.x + a.y * b1.x + a.z * b2.x + a.w * b3.x;
                s[i][1] += a.x * b0.y + a.y * b1.y + a.z * b2.y + a.w * b3.y;
                s[i][2] += a.x * b0.z + a.y * b1.z + a.z * b2.z + a.w * b3.z;
                s[i][3] += a.x * b0.w + a.y * b1.w + a.z * b2.w + a.w * b3.w;
            }
        }

        #pragma unroll
        for (int i = 0; i < 4; i++) {
            int gr = qb * 64 + ty * 4 + i;
            #pragma unroll
            for (int j = 0; j < 4; j++) {
                int gc = j0 + tx * 4 + j;
                float v = s[i][j] * scale;
                if (gc > gr) v = -1e30f;
                Ps[(ty * 4 + i) * AP + tx * 4 + j] = v;
            }
        }
        __syncthreads();

        if (tid < 64) {
            int r = tid;
            float mold = mrow[r];
            float mx = mold;
            #pragma unroll 8
            for (int k = 0; k < 64; k++) mx = fmaxf(mx, Ps[r * AP + k]);
            float c = __expf(mold - mx);
            float sum = 0.f;
            #pragma unroll 8
            for (int k = 0; k < 64; k++) {
                float p = __expf(Ps[r * AP + k] - mx);
                Ps[r * AP + k] = p;
                sum += p;
            }
            lrow[r] = lrow[r] * c + sum;
            mrow[r] = mx;
            cf[r] = c;
        }
        __syncthreads();

        #pragma unroll
        for (int i = 0; i < 4; i++) {
            float ci = cf[ty * 4 + i];
            #pragma unroll
            for (int j = 0; j < 4; j++) acc[i][j] *= ci;
        }
        #pragma unroll
        for (int kk = 0; kk < 64; kk += 4) {
            float4 v0 = *reinterpret_cast<const float4*>(&Vs[(kk + 0) * AP + tx * 4]);
            float4 v1 = *reinterpret_cast<const float4*>(&Vs[(kk + 1) * AP + tx * 4]);
            float4 v2 = *reinterpret_cast<const float4*>(&Vs[(kk + 2) * AP + tx * 4]);
            float4 v3 = *reinterpret_cast<const float4*>(&Vs[(kk + 3) * AP + tx * 4]);
            #pragma unroll
            for (int i = 0; i < 4; i++) {
                float4 p = *reinterpret_cast<const float4*>(&Ps[(ty * 4 + i) * AP + kk]);
                acc[i][0] += p.x * v0.x + p.y * v1.x + p.z * v2.x + p.w * v3.x;
                acc[i][1] += p.x * v0.y + p.y * v1.y + p.z * v2.y + p.w * v3.y;
                acc[i][2] += p.x * v0.z + p.y * v1.z + p.z * v2.z + p.w * v3.z;
                acc[i][3] += p.x * v0.w + p.y * v1.w + p.z * v2.w + p.w * v3.w;
            }
        }
        __syncthreads();
    }

    #pragma unroll
    for (int i = 0; i < 4; i++) {
        int t = qb * 64 + ty * 4 + i;
        float inv = 1.0f / lrow[ty * 4 + i];
        __half2 h0 = __floats2half2_rn(acc[i][0] * inv, acc[i][1] * inv);
        __half2 h1 = __floats2half2_rn(acc[i][2] * inv, acc[i][3] * inv);
        uint2 u = make_uint2(*reinterpret_cast<uint32_t*>(&h0),
                             *reinterpret_cast<uint32_t*>(&h1));
        *reinterpret_cast<uint2*>(
            &O[(size_t)(b * kT + t) * kD + h * kE + tx * 4]) = u;
    }
}

// ---------------------------------------------------------------------------
// Launch
// ---------------------------------------------------------------------------
extern "C" void kernel_launch(void* const* d_in, const int* in_sizes, int n_in,
                              void* d_out, int out_size)
{
    const float* x      = (const float*)d_in[0];
    const float* wq     = (const float*)d_in[1];
    const float* wk     = (const float*)d_in[2];
    const float* wv     = (const float*)d_in[3];
    const float* w_proj = (const float*)d_in[4];
    const float* b_proj = (const float*)d_in[5];
    const float* w1     = (const float*)d_in[6];
    const float* b1     = (const float*)d_in[7];
    const float* w2     = (const float*)d_in[8];
    const float* b2     = (const float*)d_in[9];
    const float* g1     = (const float*)d_in[10];
    const float* be1    = (const float*)d_in[11];
    const float* g2     = (const float*)d_in[12];
    const float* be2    = (const float*)d_in[13];
    float* out = (float*)d_out;

    float  *ln1f, *qkv, *x2, *ln2f;
    __half *ln1h, *atth, *ln2h, *hidh, *wqkvh, *wph, *w1t, *w2t;
    cudaGetSymbolAddress((void**)&ln1f,  g_ln1f);
    cudaGetSymbolAddress((void**)&ln1h,  g_ln1h);
    cudaGetSymbolAddress((void**)&qkv,   g_qkv);
    cudaGetSymbolAddress((void**)&atth,  g_atth);
    cudaGetSymbolAddress((void**)&x2,    g_x2);
    cudaGetSymbolAddress((void**)&ln2f,  g_ln2f);
    cudaGetSymbolAddress((void**)&ln2h,  g_ln2h);
    cudaGetSymbolAddress((void**)&hidh,  g_hidh);
    cudaGetSymbolAddress((void**)&wqkvh, g_wqkv);
    cudaGetSymbolAddress((void**)&wph,   g_wp);
    cudaGetSymbolAddress((void**)&w1t,   g_w1t);
    cudaGetSymbolAddress((void**)&w2t,   g_w2t);

    cudaFuncSetAttribute(attn_kernel,
                         cudaFuncAttributeMaxDynamicSharedMemorySize, ATTN_SMEM);
    cudaFuncSetAttribute(gemm_mma<0, 1, 0>,
                         cudaFuncAttributeMaxDynamicSharedMemorySize, GEMM_SMEM);
    cudaFuncSetAttribute(gemm_mma<1, 0, 1>,
                         cudaFuncAttributeMaxDynamicSharedMemorySize, GEMM_SMEM);

    // 1) LN1 (f32 residual + f16 GEMM input)
    ln_kernel<<<kM, 256>>>(x, g1, be1, ln1f, ln1h);

    // 2) Weight transposes + f16 conversion
    wqkv_t_kernel<<<dim3(kD / 32, kE / 32, 48), 256>>>(wq, wk, wv, wqkvh);
    tr_kernel<<<dim3(kD / 32, kD / 32), 256>>>(w_proj, wph, kD, kD);
    tr_kernel<<<dim3(kF / 32, kD / 32), 256>>>(w1, w1t, kD, kF);
    tr_kernel<<<dim3(kD / 32, kF / 32), 256>>>(w2, w2t, kF, kD);

    // 3) QKV GEMM: [8192,1024] @ [3072,1024]^T -> f32
    gemm_mma<0, 1, 0><<<dim3(kQKVN / 128, kM / 128), 256, GEMM_SMEM>>>(
        ln1h, wqkvh, nullptr, nullptr, qkv, nullptr, kM, kQKVN, kD);

    // 4) Causal flash attention (fp32) -> f16
    attn_kernel<<<dim3(kT / 64, kH, kB), 256, ATTN_SMEM>>>(qkv, atth);

    // 5) Output projection + bias + residual(ln1) -> x2 (f32)
    gemm_mma<0, 1, 0><<<dim3(kD / 128, kM / 128), 256, GEMM_SMEM>>>(
        atth, wph, b_proj, ln1f, x2, nullptr, kM, kD, kD);

    // 6) LN2
    ln_kernel<<<kM, 256>>>(x2, g2, be2, ln2f, ln2h);

    // 7) FFN1 + ReLU -> f16 hidden
    gemm_mma<1, 0, 1><<<dim3(kF / 128, kM / 128), 256, GEMM_SMEM>>>(
        ln2h, w1t, b1, nullptr, nullptr, hidh, kM, kF, kD);

    // 8) FFN2 + bias + residual(ln2) -> output (f32)
    gemm_mma<0, 1, 0><<<dim3(kD / 128, kM / 128), 256, GEMM_SMEM>>>(
        hidh, w2t, b2, ln2f, out, nullptr, kM, kD, kF);
}

// round 9
// speedup vs baseline: 9.2754x; 1.6947x over previous
#include <cuda_runtime.h>
#include <cuda_fp16.h>
#include <cstdint>

// ---------------------------------------------------------------------------
// Problem constants
// ---------------------------------------------------------------------------
constexpr int kB = 8;
constexpr int kT = 1024;
constexpr int kD = 1024;          // n_embd
constexpr int kH = 16;            // heads
constexpr int kE = 64;            // head size
constexpr int kF = 4096;          // ffn hidden
constexpr int kM = kB * kT;       // 8192 rows
constexpr int kQKVN = 3 * kD;     // 3072

// ---------------------------------------------------------------------------
// Scratch (device globals: allocation-free per harness rules)
// ---------------------------------------------------------------------------
__device__ __align__(16) float  g_ln1f[(size_t)kM * kD];
__device__ __align__(16) __half g_ln1h[(size_t)kM * kD];
__device__ __align__(16) __half g_qkvh[(size_t)kM * kQKVN];
__device__ __align__(16) __half g_atth[(size_t)kM * kD];
__device__ __align__(16) float  g_x2  [(size_t)kM * kD];
__device__ __align__(16) float  g_ln2f[(size_t)kM * kD];
__device__ __align__(16) __half g_ln2h[(size_t)kM * kD];
__device__ __align__(16) __half g_hidh[(size_t)kM * kF];
__device__ __align__(16) __half g_wqkv[(size_t)kQKVN * kD];   // [N=3072][K=1024]
__device__ __align__(16) __half g_wp  [(size_t)kD * kD];      // [N=1024][K=1024]
__device__ __align__(16) __half g_w1t [(size_t)kF * kD];      // [N=4096][K=1024]
__device__ __align__(16) __half g_w2t [(size_t)kD * kF];      // [N=1024][K=4096]

// ---------------------------------------------------------------------------
// Low-level helpers
// ---------------------------------------------------------------------------
__device__ __forceinline__ uint32_t smem_u32(const void* p) {
    uint32_t r;
    asm("{ .reg .u64 t; cvta.to.shared.u64 t, %1; cvt.u32.u64 %0, t; }"
        : "=r"(r) : "l"(p));
    return r;
}

__device__ __forceinline__ void cp_async16(uint32_t dst, const void* src) {
    asm volatile("cp.async.cg.shared.global [%0], [%1], 16;"
                 :: "r"(dst), "l"(src));
}

__device__ __forceinline__ void ldmatrix_x4(uint32_t* r, uint32_t addr) {
    asm volatile("ldmatrix.sync.aligned.m8n8.x4.shared.b16 {%0,%1,%2,%3}, [%4];"
                 : "=r"(r[0]), "=r"(r[1]), "=r"(r[2]), "=r"(r[3]) : "r"(addr));
}

__device__ __forceinline__ void ldmatrix_x4_trans(uint32_t* r, uint32_t addr) {
    asm volatile("ldmatrix.sync.aligned.m8n8.x4.trans.shared.b16 {%0,%1,%2,%3}, [%4];"
                 : "=r"(r[0]), "=r"(r[1]), "=r"(r[2]), "=r"(r[3]) : "r"(addr));
}

__device__ __forceinline__ void mma16816(float* d,
                                         const uint32_t* a, const uint32_t* b) {
    asm volatile(
        "mma.sync.aligned.m16n8k16.row.col.f32.f16.f16.f32 "
        "{%0,%1,%2,%3}, {%4,%5,%6,%7}, {%8,%9}, {%0,%1,%2,%3};"
        : "+f"(d[0]), "+f"(d[1]), "+f"(d[2]), "+f"(d[3])
        : "r"(a[0]), "r"(a[1]), "r"(a[2]), "r"(a[3]), "r"(b[0]), "r"(b[1]));
}

__device__ __forceinline__ uint32_t packh2(float a, float b) {
    __half2 h = __floats2half2_rn(a, b);
    return *reinterpret_cast<uint32_t*>(&h);
}

// ---------------------------------------------------------------------------
// HMMA GEMM: C[M,N] = A_h[M,K] @ B_h[N,K]^T  (+bias) (+res) (relu)
// 128x128 block tile, BK=64, 3-stage cp.async pipeline, 256 threads (8 warps,
// 64x32 warp tiles). Smem tiles: 128 rows x 128B, XOR-swizzled.
// ---------------------------------------------------------------------------
constexpr int GEMM_SMEM = 3 * 32768;   // 96 KB

template <int RELU, int W32, int W16>
__global__ __launch_bounds__(256)
void gemm_mma(const __half* __restrict__ A, const __half* __restrict__ B,
              const float* __restrict__ bias, const float* __restrict__ res,
              float* __restrict__ C32, __half* __restrict__ C16,
              int M, int N, int K)
{
    extern __shared__ char smem[];
    uint32_t sb = smem_u32(smem);

    const int tid  = threadIdx.x;
    const int wid  = tid >> 5;
    const int lane = tid & 31;
    const int wm = (wid & 1) * 64;        // warp row offset in tile
    const int wn = (wid >> 1) * 32;       // warp col offset in tile
    const int row0 = blockIdx.y * 128;
    const int col0 = blockIdx.x * 128;
    const __half* Ab = A + (size_t)row0 * K;
    const __half* Bb = B + (size_t)col0 * K;
    const int nch = K >> 6;               // chunks of K=64

    auto load_chunk = [&](int c, int s) {
        uint32_t base = sb + (uint32_t)s * 32768u;
        const __half* Ap = Ab + c * 64;
        const __half* Bp = Bb + c * 64;
        #pragma unroll
        for (int j = 0; j < 4; j++) {
            int idx = tid + j * 256;              // 0..1023
            int r  = idx >> 3;
            int cc = idx & 7;
            uint32_t off = (uint32_t)(r * 128 + ((cc ^ (r & 7)) << 4));
            cp_async16(base + off,         Ap + (size_t)r * K + cc * 8);
            cp_async16(base + 16384 + off, Bp + (size_t)r * K + cc * 8);
        }
        asm volatile("cp.async.commit_group;" ::: "memory");
    };

    float acc[4][4][4];
    #pragma unroll
    for (int i = 0; i < 4; i++)
        #pragma unroll
        for (int j = 0; j < 4; j++)
            #pragma unroll
            for (int q = 0; q < 4; q++) acc[i][j][q] = 0.f;

    load_chunk(0, 0);
    load_chunk(1, 1);

    for (int i = 0; i < nch; i++) {
        if (i < nch - 1) asm volatile("cp.async.wait_group 1;" ::: "memory");
        else             asm volatile("cp.async.wait_group 0;" ::: "memory");
        __syncthreads();

        if (i + 2 < nch) load_chunk(i + 2, (i + 2) % 3);

        uint32_t abase = sb + (uint32_t)(i % 3) * 32768u;
        uint32_t bbase = abase + 16384;

        #pragma unroll
        for (int kk = 0; kk < 4; kk++) {          // 4 k-steps of 16
            uint32_t af[4][4];
            #pragma unroll
            for (int mt = 0; mt < 4; mt++) {
                int m  = wm + mt * 16 + (lane & 7) + ((lane >> 3) & 1) * 8;
                int kc = kk * 2 + (lane >> 4);
                ldmatrix_x4(af[mt],
                            abase + (uint32_t)(m * 128 + ((kc ^ (m & 7)) << 4)));
            }
            uint32_t bf[2][4];
            #pragma unroll
            for (int nb = 0; nb < 2; nb++) {
                int n  = wn + nb * 16 + (lane & 7) + (lane >> 4) * 8;
                int kc = kk * 2 + ((lane >> 3) & 1);
                ldmatrix_x4(bf[nb],
                            bbase + (uint32_t)(n * 128 + ((kc ^ (n & 7)) << 4)));
            }
            #pragma unroll
            for (int mt = 0; mt < 4; mt++)
                #pragma unroll
                for (int nt = 0; nt < 4; nt++)
                    mma16816(acc[mt][nt], af[mt], bf[nt >> 1] + (nt & 1) * 2);
        }
    }

    #pragma unroll
    for (int mt = 0; mt < 4; mt++) {
        #pragma unroll
        for (int h = 0; h < 2; h++) {
            int r = row0 + wm + mt * 16 + (lane >> 2) + h * 8;
            size_t rowN = (size_t)r * N;
            #pragma unroll
            for (int nt = 0; nt < 4; nt++) {
                int c = col0 + wn + nt * 8 + (lane & 3) * 2;
                float v0 = acc[mt][nt][h * 2 + 0];
                float v1 = acc[mt][nt][h * 2 + 1];
                if (bias) { v0 += bias[c]; v1 += bias[c + 1]; }
                if (res) {
                    float2 r2 = *reinterpret_cast<const float2*>(res + rowN + c);
                    v0 += r2.x; v1 += r2.y;
                }
                if (RELU) { v0 = fmaxf(v0, 0.f); v1 = fmaxf(v1, 0.f); }
                if (W32) {
                    float2 o = make_float2(v0, v1);
                    *reinterpret_cast<float2*>(C32 + rowN + c) = o;
                }
                if (W16) {
                    __half2 hh = __floats2half2_rn(v0, v1);
                    *reinterpret_cast<__half2*>(C16 + rowN + c) = hh;
                }
            }
        }
    }
}

// ---------------------------------------------------------------------------
// LayerNorm: one block per row of 1024; writes fp32 + fp16
// ---------------------------------------------------------------------------
__global__ __launch_bounds__(256) void ln_kernel(
    const float* __restrict__ x, const float* __restrict__ g,
    const float* __restrict__ b, float* __restrict__ outf,
    __half* __restrict__ outh)
{
    int row = blockIdx.x;
    int tid = threadIdx.x;
    const float* xr = x + (size_t)row * kD;

    float4 v = *reinterpret_cast<const float4*>(&xr[tid * 4]);
    float s  = v.x + v.y + v.z + v.w;
    float s2 = v.x * v.x + v.y * v.y + v.z * v.z + v.w * v.w;
    #pragma unroll
    for (int o = 16; o > 0; o >>= 1) {
        s  += __shfl_xor_sync(0xffffffffu, s,  o);
        s2 += __shfl_xor_sync(0xffffffffu, s2, o);
    }
    __shared__ float red[16];
    __shared__ float sh_mean, sh_rstd;
    int w = tid >> 5, l = tid & 31;
    if (l == 0) { red[w] = s; red[8 + w] = s2; }
    __syncthreads();
    if (tid == 0) {
        float S = 0.f, S2 = 0.f;
        #pragma unroll
        for (int i = 0; i < 8; i++) { S += red[i]; S2 += red[8 + i]; }
        float mean = S * (1.0f / kD);
        float var  = S2 * (1.0f / kD) - mean * mean;
        sh_mean = mean;
        sh_rstd = rsqrtf(var + 1e-5f);
    }
    __syncthreads();
    float mean = sh_mean, rstd = sh_rstd;
    float4 gv = *reinterpret_cast<const float4*>(&g[tid * 4]);
    float4 bv = *reinterpret_cast<const float4*>(&b[tid * 4]);
    float4 o4;
    o4.x = (v.x - mean) * rstd * gv.x + bv.x;
    o4.y = (v.y - mean) * rstd * gv.y + bv.y;
    o4.z = (v.z - mean) * rstd * gv.z + bv.z;
    o4.w = (v.w - mean) * rstd * gv.w + bv.w;
    *reinterpret_cast<float4*>(&outf[(size_t)row * kD + tid * 4]) = o4;
    __half2 h0 = __floats2half2_rn(o4.x, o4.y);
    __half2 h1 = __floats2half2_rn(o4.z, o4.w);
    uint2 u = make_uint2(*reinterpret_cast<uint32_t*>(&h0),
                         *reinterpret_cast<uint32_t*>(&h1));
    *reinterpret_cast<uint2*>(&outh[(size_t)row * kD + tid * 4]) = u;
}

// ---------------------------------------------------------------------------
// Weight transpose+convert: wq/wk/wv [H,D,E] f32 -> [N=3072][K=1024] f16
// ---------------------------------------------------------------------------
__global__ __launch_bounds__(256) void wqkv_t_kernel(
    const float* __restrict__ wq, const float* __restrict__ wk,
    const float* __restrict__ wv, __half* __restrict__ out)
{
    __shared__ float tile[32][33];
    int z = blockIdx.z;
    int sec = z >> 4, h = z & 15;
    const float* in = ((sec == 0) ? wq : (sec == 1) ? wk : wv) +
                      (size_t)h * kD * kE;
    int d0 = blockIdx.x * 32, e0 = blockIdx.y * 32;
    int x = threadIdx.x & 31, y0 = threadIdx.x >> 5;   // y0 in 0..7
    #pragma unroll
    for (int j = 0; j < 32; j += 8)
        tile[y0 + j][x] = in[(size_t)(d0 + y0 + j) * kE + e0 + x];
    __syncthreads();
    #pragma unroll
    for (int j = 0; j < 32; j += 8)
        out[(size_t)(sec * kD + h * kE + e0 + y0 + j) * kD + d0 + x] =
            __float2half(tile[x][y0 + j]);
}

// Generic transpose+convert: in [R,C] f32 -> out [C,R] f16
__global__ __launch_bounds__(256) void tr_kernel(
    const float* __restrict__ in, __half* __restrict__ out, int R, int C)
{
    __shared__ float tile[32][33];
    int r0 = blockIdx.y * 32, c0 = blockIdx.x * 32;
    int x = threadIdx.x & 31, y0 = threadIdx.x >> 5;
    #pragma unroll
    for (int j = 0; j < 32; j += 8)
        tile[y0 + j][x] = in[(size_t)(r0 + y0 + j) * C + c0 + x];
    __syncthreads();
    #pragma unroll
    for (int j = 0; j < 32; j += 8)
        out[(size_t)(c0 + y0 + j) * R + r0 + x] = __float2half(tile[x][y0 + j]);
}

// ---------------------------------------------------------------------------
// Causal flash attention, f16 HMMA (FlashAttention-2 register pipeline).
// Block = 128 queries of one (b,h); 8 warps x 16 query rows; key tiles of 64.
// Q/K/V f16 from the fused QKV buffer; S and O accumulate in f32.
// Smem: Q 16KB + 3 x (K 8KB + V 8KB) = 64KB dynamic.
// ---------------------------------------------------------------------------
constexpr int ATTN_SMEM = 16384 + 3 * 16384;   // 65536

__global__ __launch_bounds__(256) void attn_mma_kernel(
    const __half* __restrict__ QKV, __half* __restrict__ O)
{
    extern __shared__ char smem[];
    uint32_t sb = smem_u32(smem);
    uint32_t qsm = sb;

    const int qb = blockIdx.x, h = blockIdx.y, b = blockIdx.z;
    const int tid = threadIdx.x;
    const int wid = tid >> 5, lane = tid & 31;
    const int g  = lane >> 2, t4 = lane & 3;
    const int q0 = qb * 128;
    const int nt = 2 * qb + 2;              // key tiles of 64
    const int qrow0 = q0 + wid * 16;

    const __half* base = QKV + (size_t)(b * kT) * kQKVN + h * kE;

    // Q tile: 128 rows x 128B
    #pragma unroll
    for (int j = 0; j < 4; j++) {
        int idx = tid + j * 256;
        int r = idx >> 3, cc = idx & 7;
        uint32_t off = (uint32_t)(r * 128 + ((cc ^ (r & 7)) << 4));
        cp_async16(qsm + off, base + (size_t)(q0 + r) * kQKVN + cc * 8);
    }

    auto load_kv = [&](int j, int s) {
        uint32_t kb = sb + 16384 + (uint32_t)s * 16384u;
        const __half* Kp = base + kD;
        const __half* Vp = base + 2 * kD;
        #pragma unroll
        for (int jj = 0; jj < 2; jj++) {
            int idx = tid + jj * 256;
            int r = idx >> 3, cc = idx & 7;
            uint32_t off = (uint32_t)(r * 128 + ((cc ^ (r & 7)) << 4));
            cp_async16(kb + off,        Kp + (size_t)(j * 64 + r) * kQKVN + cc * 8);
            cp_async16(kb + 8192 + off, Vp + (size_t)(j * 64 + r) * kQKVN + cc * 8);
        }
        asm volatile("cp.async.commit_group;" ::: "memory");
    };

    load_kv(0, 0);     // group 0 (also carries the Q loads)
    load_kv(1, 1);     // group 1 (nt >= 2 always)

    uint32_t qf[4][4];
    float oacc[8][4];
    #pragma unroll
    for (int t = 0; t < 8; t++)
        #pragma unroll
        for (int q = 0; q < 4; q++) oacc[t][q] = 0.f;
    float m0 = -1e30f, m1 = -1e30f, l0 = 0.f, l1 = 0.f;
    const float scale = 0.125f;

    for (int i = 0; i < nt; i++) {
        if (i < nt - 1) asm volatile("cp.async.wait_group 1;" ::: "memory");
        else            asm volatile("cp.async.wait_group 0;" ::: "memory");
        __syncthreads();

        if (i == 0) {
            #pragma unroll
            for (int kc = 0; kc < 4; kc++) {
                int m  = wid * 16 + (lane & 7) + ((lane >> 3) & 1) * 8;
                int ch = kc * 2 + (lane >> 4);
                ldmatrix_x4(qf[kc],
                            qsm + (uint32_t)(m * 128 + ((ch ^ (m & 7)) << 4)));
            }
        }
        if (i + 2 < nt) load_kv(i + 2, (i + 2) % 3);

        uint32_t kb = sb + 16384 + (uint32_t)(i % 3) * 16384u;
        uint32_t vb = kb + 8192;

        // ---- S = Q K^T ----
        float sacc[8][4];
        #pragma unroll
        for (int t = 0; t < 8; t++)
            #pragma unroll
            for (int q = 0; q < 4; q++) sacc[t][q] = 0.f;

        #pragma unroll
        for (int kc = 0; kc < 4; kc++) {
            #pragma unroll
            for (int np = 0; np < 4; np++) {
                int n  = np * 16 + (lane & 7) + (lane >> 4) * 8;
                int ch = kc * 2 + ((lane >> 3) & 1);
                uint32_t bf[4];
                ldmatrix_x4(bf, kb + (uint32_t)(n * 128 + ((ch ^ (n & 7)) << 4)));
                mma16816(sacc[np * 2 + 0], qf[kc], bf);
                mma16816(sacc[np * 2 + 1], qf[kc], bf + 2);
            }
        }

        // ---- scale + causal mask ----
        const int j0 = i * 64;
        const int gr0 = qrow0 + g, gr1 = gr0 + 8;
        const bool need_mask = (j0 + 63 > qrow0);
        #pragma unroll
        for (int t = 0; t < 8; t++) {
            int gc = j0 + t * 8 + t4 * 2;
            float s0 = sacc[t][0] * scale, s1 = sacc[t][1] * scale;
            float s2 = sacc[t][2] * scale, s3 = sacc[t][3] * scale;
            if (need_mask) {
                if (gc     > gr0) s0 = -1e30f;
                if (gc + 1 > gr0) s1 = -1e30f;
                if (gc     > gr1) s2 = -1e30f;
                if (gc + 1 > gr1) s3 = -1e30f;
            }
            sacc[t][0] = s0; sacc[t][1] = s1; sacc[t][2] = s2; sacc[t][3] = s3;
        }

        // ---- online softmax (quad reduction over lanes t4) ----
        float rmax0 = -1e30f, rmax1 = -1e30f;
        #pragma unroll
        for (int t = 0; t < 8; t++) {
            rmax0 = fmaxf(rmax0, fmaxf(sacc[t][0], sacc[t][1]));
            rmax1 = fmaxf(rmax1, fmaxf(sacc[t][2], sacc[t][3]));
        }
        rmax0 = fmaxf(rmax0, __shfl_xor_sync(0xffffffffu, rmax0, 1));
        rmax0 = fmaxf(rmax0, __shfl_xor_sync(0xffffffffu, rmax0, 2));
        rmax1 = fmaxf(rmax1, __shfl_xor_sync(0xffffffffu, rmax1, 1));
        rmax1 = fmaxf(rmax1, __shfl_xor_sync(0xffffffffu, rmax1, 2));

        float mn0 = fmaxf(m0, rmax0), mn1 = fmaxf(m1, rmax1);
        float f0 = __expf(m0 - mn0),  f1 = __expf(m1 - mn1);
        float sum0 = 0.f, sum1 = 0.f;
        #pragma unroll
        for (int t = 0; t < 8; t++) {
            float p0 = __expf(sacc[t][0] - mn0);
            float p1 = __expf(sacc[t][1] - mn0);
            float p2 = __expf(sacc[t][2] - mn1);
            float p3 = __expf(sacc[t][3] - mn1);
            sacc[t][0] = p0; sacc[t][1] = p1; sacc[t][2] = p2; sacc[t][3] = p3;
            sum0 += p0 + p1; sum1 += p2 + p3;
        }
        sum0 += __shfl_xor_sync(0xffffffffu, sum0, 1);
        sum0 += __shfl_xor_sync(0xffffffffu, sum0, 2);
        sum1 += __shfl_xor_sync(0xffffffffu, sum1, 1);
        sum1 += __shfl_xor_sync(0xffffffffu, sum1, 2);
        l0 = l0 * f0 + sum0; m0 = mn0;
        l1 = l1 * f1 + sum1; m1 = mn1;

        #pragma unroll
        for (int t = 0; t < 8; t++) {
            oacc[t][0] *= f0; oacc[t][1] *= f0;
            oacc[t][2] *= f1; oacc[t][3] *= f1;
        }

        // ---- O += P V ----  (P regs -> A-frags directly)
        #pragma unroll
        for (int kc = 0; kc < 4; kc++) {
            uint32_t pa[4];
            pa[0] = packh2(sacc[2 * kc][0],     sacc[2 * kc][1]);
            pa[1] = packh2(sacc[2 * kc][2],     sacc[2 * kc][3]);
            pa[2] = packh2(sacc[2 * kc + 1][0], sacc[2 * kc + 1][1]);
            pa[3] = packh2(sacc[2 * kc + 1][2], sacc[2 * kc + 1][3]);
            #pragma unroll
            for (int np = 0; np < 4; np++) {
                int kk = kc * 16 + (lane & 7) + ((lane >> 3) & 1) * 8;  // V row
                int ch = np * 2 + (lane >> 4);                          // E chunk
                uint32_t bf[4];
                ldmatrix_x4_trans(bf,
                    vb + (uint32_t)(kk * 128 + ((ch ^ (kk & 7)) << 4)));
                mma16816(oacc[np * 2 + 0], pa, bf);
                mma16816(oacc[np * 2 + 1], pa, bf + 2);
            }
        }
    }

    // ---- normalize + write ----
    float inv0 = 1.0f / l0, inv1 = 1.0f / l1;
    size_t row0 = (size_t)(b * kT + qrow0 + g) * kD;
    size_t row1 = row0 + (size_t)8 * kD;
    #pragma unroll
    for (int t = 0; t < 8; t++) {
        int col = h * kE + t * 8 + t4 * 2;
        __half2 o0 = __floats2half2_rn(oacc[t][0] * inv0, oacc[t][1] * inv0);
        __half2 o1 = __floats2half2_rn(oacc[t][2] * inv1, oacc[t][3] * inv1);
        *reinterpret_cast<__half2*>(O + row0 + col) = o0;
        *reinterpret_cast<__half2*>(O + row1 + col) = o1;
    }
}

// ---------------------------------------------------------------------------
// Launch
// ---------------------------------------------------------------------------
extern "C" void kernel_launch(void* const* d_in, const int* in_sizes, int n_in,
                              void* d_out, int out_size)
{
    const float* x      = (const float*)d_in[0];
    const float* wq     = (const float*)d_in[1];
    const float* wk     = (const float*)d_in[2];
    const float* wv     = (const float*)d_in[3];
    const float* w_proj = (const float*)d_in[4];
    const float* b_proj = (const float*)d_in[5];
    const float* w1     = (const float*)d_in[6];
    const float* b1     = (const float*)d_in[7];
    const float* w2     = (const float*)d_in[8];
    const float* b2     = (const float*)d_in[9];
    const float* g1     = (const float*)d_in[10];
    const float* be1    = (const float*)d_in[11];
    const float* g2     = (const float*)d_in[12];
    const float* be2    = (const float*)d_in[13];
    float* out = (float*)d_out;

    float  *ln1f, *x2, *ln2f;
    __half *ln1h, *qkvh, *atth, *ln2h, *hidh, *wqkvh, *wph, *w1t, *w2t;
    cudaGetSymbolAddress((void**)&ln1f,  g_ln1f);
    cudaGetSymbolAddress((void**)&ln1h,  g_ln1h);
    cudaGetSymbolAddress((void**)&qkvh,  g_qkvh);
    cudaGetSymbolAddress((void**)&atth,  g_atth);
    cudaGetSymbolAddress((void**)&x2,    g_x2);
    cudaGetSymbolAddress((void**)&ln2f,  g_ln2f);
    cudaGetSymbolAddress((void**)&ln2h,  g_ln2h);
    cudaGetSymbolAddress((void**)&hidh,  g_hidh);
    cudaGetSymbolAddress((void**)&wqkvh, g_wqkv);
    cudaGetSymbolAddress((void**)&wph,   g_wp);
    cudaGetSymbolAddress((void**)&w1t,   g_w1t);
    cudaGetSymbolAddress((void**)&w2t,   g_w2t);

    cudaFuncSetAttribute(attn_mma_kernel,
                         cudaFuncAttributeMaxDynamicSharedMemorySize, ATTN_SMEM);
    cudaFuncSetAttribute(gemm_mma<0, 1, 0>,
                         cudaFuncAttributeMaxDynamicSharedMemorySize, GEMM_SMEM);
    cudaFuncSetAttribute(gemm_mma<0, 0, 1>,
                         cudaFuncAttributeMaxDynamicSharedMemorySize, GEMM_SMEM);
    cudaFuncSetAttribute(gemm_mma<1, 0, 1>,
                         cudaFuncAttributeMaxDynamicSharedMemorySize, GEMM_SMEM);

    // 1) LN1 (f32 residual + f16 GEMM input)
    ln_kernel<<<kM, 256>>>(x, g1, be1, ln1f, ln1h);

    // 2) Weight transposes + f16 conversion
    wqkv_t_kernel<<<dim3(kD / 32, kE / 32, 48), 256>>>(wq, wk, wv, wqkvh);
    tr_kernel<<<dim3(kD / 32, kD / 32), 256>>>(w_proj, wph, kD, kD);
    tr_kernel<<<dim3(kF / 32, kD / 32), 256>>>(w1, w1t, kD, kF);
    tr_kernel<<<dim3(kD / 32, kF / 32), 256>>>(w2, w2t, kF, kD);

    // 3) QKV GEMM: [8192,1024] @ [3072,1024]^T -> f16
    gemm_mma<0, 0, 1><<<dim3(kQKVN / 128, kM / 128), 256, GEMM_SMEM>>>(
        ln1h, wqkvh, nullptr, nullptr, nullptr, qkvh, kM, kQKVN, kD);

    // 4) Causal flash attention (f16 HMMA) -> f16
    attn_mma_kernel<<<dim3(kT / 128, kH, kB), 256, ATTN_SMEM>>>(qkvh, atth);

    // 5) Output projection + bias + residual(ln1) -> x2 (f32)
    gemm_mma<0, 1, 0><<<dim3(kD / 128, kM / 128), 256, GEMM_SMEM>>>(
        atth, wph, b_proj, ln1f, x2, nullptr, kM, kD, kD);

    // 6) LN2
    ln_kernel<<<kM, 256>>>(x2, g2, be2, ln2f, ln2h);

    // 7) FFN1 + ReLU -> f16 hidden
    gemm_mma<1, 0, 1><<<dim3(kF / 128, kM / 128), 256, GEMM_SMEM>>>(
        ln2h, w1t, b1, nullptr, nullptr, hidh, kM, kF, kD);

    // 8) FFN2 + bias + residual(ln2) -> output (f32)
    gemm_mma<0, 1, 0><<<dim3(kD / 128, kM / 128), 256, GEMM_SMEM>>>(
        hidh, w2t, b2, ln2f, out, nullptr, kM, kD, kF);
}